// round 9
// baseline (speedup 1.0000x reference)
#include <cuda_runtime.h>
#include <cuda_fp16.h>
#include <cstdint>

// Problem constants
#define T_STEPS 512
#define BATCH   256
#define DIN     128
#define HID     512
#define KTOT    640          // DIN + HID

// Tiling: 64 CTAs; CTA (g2, jn) handles batch groups {2*g2, 2*g2+1}, n-slice jn.
#define P_B 8                // batch groups
#define P_N 16               // n-slices per group
#define B_TILE 32            // batch rows per tile (M)
#define N_SLICE 32           // H columns per tile
#define NCHUNK 5             // 640 / 128
#define NKG 8                // kg16 groups per chunk
#define KGG_TOT 40           // 640 / 16
#define NTHREADS 512
#define GRID 64

// Shared memory layout (uint32 units)
#define OFF_WF  0            // B frag staging: 40*4*32*4 = 20480 u32 (80KB)
#define OFF_Z   20480        // 2 groups * 5 slots * 2048 u32 (80KB)
#define OFF_EPI 40960        // 4 wk-buffers * 32*66 = 8448
#define OFF_BC  49408        // 32
#define OFF_BT  49440        // 32
#define SMEM_U32 49472
#define SMEM_BYTES (SMEM_U32 * 4)   // 197888 B

#define ZBUF_BYTES 8192
#define ZGRP_BYTES (NCHUNK * ZBUF_BYTES)   // 40960 (bits 13+, carry-free vs swizzle)
#define HZ_GRP_BYTES (4 * ZBUF_BYTES)      // 32768 per (buf, group)

// Persistent device state.
// g_hz: hidden state fp16, PRE-SWIZZLED smem fragment layout, [buf][group][chunk].
__device__ __align__(16) char g_hz[2][P_B][4][ZBUF_BYTES];
__device__ float    g_ypart[2][BATCH][P_N];
__device__ unsigned g_count[P_B];   // zero-init; returns to 0 each launch
__device__ unsigned g_sense[P_B];   // 512 toggles/launch -> back to 0 (replay-safe)

__device__ __forceinline__ void mma_f16(float* c, unsigned a0, unsigned a1,
                                        unsigned a2, unsigned a3,
                                        unsigned b0, unsigned b1) {
    asm("mma.sync.aligned.m16n8k16.row.col.f32.f16.f16.f32 "
        "{%0,%1,%2,%3},{%4,%5,%6,%7},{%8,%9},{%0,%1,%2,%3};"
        : "+f"(c[0]), "+f"(c[1]), "+f"(c[2]), "+f"(c[3])
        : "r"(a0), "r"(a1), "r"(a2), "r"(a3), "r"(b0), "r"(b1));
}

__device__ __forceinline__ void ldsm_x4(unsigned& a0, unsigned& a1,
                                        unsigned& a2, unsigned& a3, unsigned saddr) {
    asm volatile("ldmatrix.sync.aligned.m8n8.x4.shared.b16 {%0,%1,%2,%3}, [%4];"
                 : "=r"(a0), "=r"(a1), "=r"(a2), "=r"(a3) : "r"(saddr));
}

// Store one fp32 chunk into smem as fp16; XOR swizzle on the COMPLETE low-13-bit
// byte offset: (m*256 + k*2) ^ ((m&7)<<4). Used only for x chunks (slot 0).
__device__ __forceinline__ void st_chunk(const float4* v, char* zbuf, int tid) {
#pragma unroll
    for (int i = 0; i < 2; i++) {
        int f  = i * NTHREADS + tid;
        int m  = f >> 5;
        int k4 = (f & 31) * 4;
        unsigned off = (unsigned)(m * 256 + k4 * 2) ^ (((unsigned)m & 7u) << 4);
        __half2 h01 = __float22half2_rn(make_float2(v[i].x, v[i].y));
        __half2 h23 = __float22half2_rn(make_float2(v[i].z, v[i].w));
        uint2 pk;
        pk.x = *(unsigned*)&h01;
        pk.y = *(unsigned*)&h23;
        *(uint2*)(zbuf + off) = pk;
    }
}

__global__ void __launch_bounds__(NTHREADS, 1)
liquid_kernel(const float* __restrict__ x_seq,
              const float* __restrict__ Wc, const float* __restrict__ bc,
              const float* __restrict__ Wt, const float* __restrict__ bt,
              const float* __restrict__ Wo, const float* __restrict__ bo,
              float* __restrict__ out) {
    extern __shared__ unsigned smem[];
    unsigned* sWf  = smem + OFF_WF;
    char*     sZ   = (char*)(smem + OFF_Z);
    float*    sEpi = (float*)(smem + OFF_EPI);
    float*    sBc  = (float*)(smem + OFF_BC);
    float*    sBt  = (float*)(smem + OFF_BT);

    const int tid  = threadIdx.x;
    const int g2   = blockIdx.x >> 4;    // pair index 0..3
    const int jn   = blockIdx.x & 15;    // n-slice 0..15
    const int n0   = jn * N_SLICE;
    const int lane = tid & 31;
    const int wid  = tid >> 5;           // 0..15
    const int wm   = wid & 1;            // M half (16 rows)
    const int wn   = (wid >> 1) & 1;     // N half (32 combined cols)
    const int wk   = wid >> 2;           // K quarter (2 kg16 per chunk)

    // ---- init: weights into B-fragment layout (fp16) in smem staging ----
    for (int e = tid; e < KGG_TOT * 4 * 32 * 4; e += NTHREADS) {
        int q    = e & 3;
        int l    = (e >> 2) & 31;
        int ntp  = (e >> 7) & 3;
        int kgg  = e >> 9;
        int nt   = 2 * ntp + (q >> 1);
        int k0   = kgg * 16 + (l & 3) * 2 + (q & 1) * 8;
        int cc   = nt * 8 + (l >> 2);
        const float* W = (cc < N_SLICE) ? (Wc + n0 + cc) : (Wt + n0 + cc - N_SLICE);
        float w0 = W[(size_t)k0 * HID];
        float w1 = W[(size_t)(k0 + 1) * HID];
        __half2 h = __float22half2_rn(make_float2(w0, w1));
        sWf[e] = *(unsigned*)&h;
    }
    if (tid < N_SLICE) { sBc[tid] = bc[n0 + tid]; sBt[tid] = bt[n0 + tid]; }
    const float wo_v = Wo[n0 + lane];
    const float bo_v = bo[0];
    __syncthreads();

    // ---- this warp's B fragments -> REGISTERS (shared by BOTH groups) ----
    uint4 bf[10][2];
#pragma unroll
    for (int t = 0; t < 10; t++) {
        int kgg = (t >> 1) * NKG + wk * 2 + (t & 1);
#pragma unroll
        for (int tp = 0; tp < 2; tp++) {
            int ntp = wn * 2 + tp;
            bf[t][tp] = *(const uint4*)(sWf + ((kgg * 4 + ntp) * 32 + lane) * 4);
        }
    }

    // Per-thread staging coordinates (step/group-invariant)
    const int sm0 = tid >> 5;
    const int sk0 = (tid & 31) * 4;
    const int sm1 = (NTHREADS + tid) >> 5;

    // ldmatrix base offsets; swizzle on complete low-13-bit offset; group/chunk
    // offsets are bits 13+ (carry-free).
    const int arow = wm * 16 + ((lane >> 3) & 1) * 8 + (lane & 7);
    const int acol = ((lane >> 4) & 1) * 16;
    const unsigned zsh = (unsigned)__cvta_generic_to_shared(sZ);
    unsigned aoff[2];
#pragma unroll
    for (int i = 0; i < 2; i++) {
        int kg = wk * 2 + i;
        aoff[i] = zsh + (((unsigned)(arow * 256 + kg * 32 + acol)) ^
                         (((unsigned)arow & 7u) << 4));
    }

    // h-store byte offsets within a (buf, group) hz block (step-invariant)
    const int hcol = n0 + lane;
    const unsigned hz_off0 = (unsigned)((hcol >> 7) * ZBUF_BYTES) +
        (((unsigned)((wid) * 256 + (hcol & 127) * 2)) ^ (((unsigned)wid & 7u) << 4));
    const unsigned hz_off1 = (unsigned)((hcol >> 7) * ZBUF_BYTES) +
        (((unsigned)((16 + wid) * 256 + (hcol & 127) * 2)) ^ (((unsigned)(16 + wid) & 7u) << 4));

    float h_loc[2][2] = {{0.f, 0.f}, {0.f, 0.f}};
    unsigned lsense[2] = {0u, 0u};

    // Prestage x chunk for step 0 for both groups
#pragma unroll
    for (int gi = 0; gi < 2; gi++) {
        const int b0 = (g2 * 2 + gi) * B_TILE;
        float4 vx[2];
        const float* src = x_seq + (size_t)b0 * DIN;
        vx[0] = *(const float4*)(src + (size_t)sm0 * DIN + sk0);
        vx[1] = *(const float4*)(src + (size_t)sm1 * DIN + sk0);
        st_chunk(vx, sZ + gi * ZGRP_BYTES, tid);
    }
    __syncthreads();

    for (int s = 0; s < T_STEPS; s++) {
        const int p = s & 1;

#pragma unroll
        for (int gi = 0; gi < 2; gi++) {
            const int gb = g2 * 2 + gi;
            const int b0 = gb * B_TILE;
            char* zg = sZ + gi * ZGRP_BYTES;

            // ---- WAIT for this group's step-(s-1) barrier (usually done) ----
            if (s > 0 && tid == 0) {
                unsigned v;
                do {
                    asm volatile("ld.acquire.gpu.global.u32 %0, [%1];"
                                 : "=r"(v) : "l"(&g_sense[gb]) : "memory");
                } while (v != lsense[gi]);
            }
            __syncthreads();

            // ---- stage h chunks 1..4 (identity copy, pre-swizzled fp16) ----
            {
                uint4 hv[4];
                if (s > 0) {
                    const char* hb = &g_hz[p][gb][0][0];
#pragma unroll
                    for (int c = 0; c < 4; c++)
                        hv[c] = __ldcg((const uint4*)(hb + c * ZBUF_BYTES) + tid);
                } else {
                    hv[0] = hv[1] = hv[2] = hv[3] = make_uint4(0u, 0u, 0u, 0u);
                }
#pragma unroll
                for (int c = 0; c < 4; c++)
                    *((uint4*)(zg + (c + 1) * ZBUF_BYTES) + tid) = hv[c];
            }

            // ---- finish y for previous step (warp 0, overlaps staging) ----
            if (s > 0 && tid < 32) {
                int r = tid >> 4, j = tid & 15;
                int b = b0 + jn * 2 + r;
                float v = __ldcg(&g_ypart[p ^ 1][b][j]);
#pragma unroll
                for (int o = 8; o; o >>= 1) v += __shfl_xor_sync(0xffffffffu, v, o);
                if (j == 0) out[(size_t)(s - 1) * BATCH + b] = v + bo_v;
            }
            __syncthreads();

            // ---- GEMM: 5 chunks, B fragments from registers ----
            float acc[4][4] = {};
            const unsigned goff = (unsigned)(gi * ZGRP_BYTES);
#pragma unroll
            for (int t = 0; t < 10; t++) {
                unsigned c = (unsigned)(t >> 1);
                unsigned a0, a1, a2, a3;
                ldsm_x4(a0, a1, a2, a3, aoff[t & 1] + goff + c * ZBUF_BYTES);
#pragma unroll
                for (int tp = 0; tp < 2; tp++) {
                    mma_f16(acc[tp * 2 + 0], a0, a1, a2, a3, bf[t][tp].x, bf[t][tp].y);
                    mma_f16(acc[tp * 2 + 1], a0, a1, a2, a3, bf[t][tp].z, bf[t][tp].w);
                }
            }

            // ---- scatter partial accumulators to per-wk epilogue buffers ----
            {
                float* eb = sEpi + wk * 2112;
                int row = wm * 16 + (lane >> 2);
#pragma unroll
                for (int t = 0; t < 4; t++) {
                    int col = wn * 32 + t * 8 + (lane & 3) * 2;
                    *(float2*)&eb[row * 66 + col]       = make_float2(acc[t][0], acc[t][1]);
                    *(float2*)&eb[(row + 8) * 66 + col] = make_float2(acc[t][2], acc[t][3]);
                }
            }

            // ---- issue next step's x LDG for this group ----
            float4 vx[2];
            if (s + 1 < T_STEPS) {
                const float* src = x_seq + ((size_t)(s + 1) * BATCH + b0) * DIN;
                vx[0] = *(const float4*)(src + (size_t)sm0 * DIN + sk0);
                vx[1] = *(const float4*)(src + (size_t)sm1 * DIN + sk0);
            }
            __syncthreads();

            // ---- epilogue: reduce, activations, h update ----
            float tau_sv[2];
            char* hz_base = (char*)g_hz + ((size_t)(p ^ 1) * P_B + gb) * HZ_GRP_BYTES;
#pragma unroll
            for (int i = 0; i < 2; i++) {
                int b  = i * 16 + wid;
                int nl = lane;
                float uc = sBc[nl], ut = sBt[nl];
#pragma unroll
                for (int q = 0; q < 4; q++) {
                    uc += sEpi[q * 2112 + b * 66 + nl];
                    ut += sEpi[q * 2112 + b * 66 + nl + 32];
                }
                float ea   = __expf(-2.f * fabsf(uc));
                float cand = copysignf(__fdividef(1.f - ea, 1.f + ea), uc);
                float sg   = __fdividef(1.f, 1.f + __expf(-ut));
                float tau  = 0.2f + 1.8f * sg;
                tau_sv[i]  = tau;
                float h    = h_loc[gi][i];
                float hn   = h + 0.1f * __fdividef(cand - h, tau);
                h_loc[gi][i] = hn;
                *(__half*)(hz_base + (i == 0 ? hz_off0 : hz_off1)) = __float2half_rn(hn);

                float pp = hn * wo_v;
#pragma unroll
                for (int o = 16; o; o >>= 1) pp += __shfl_xor_sync(0xffffffffu, pp, o);
                if (lane == 0) g_ypart[s & 1][b0 + b][jn] = pp;
            }

            // ---- ARRIVE at this group's barrier (no wait here) ----
            __syncthreads();
            if (tid == 0) {
                lsense[gi] ^= 1u;
                unsigned old;
                asm volatile("atom.add.release.gpu.global.u32 %0, [%1], %2;"
                             : "=r"(old) : "l"(&g_count[gb]), "r"(1u) : "memory");
                if (old == P_N - 1u) {
                    g_count[gb] = 0u;
                    asm volatile("st.release.gpu.global.u32 [%0], %1;"
                                 :: "l"(&g_sense[gb]), "r"(lsense[gi]) : "memory");
                }
            }
            // tau never read cross-CTA: store outside the ordered region.
#pragma unroll
            for (int i = 0; i < 2; i++) {
                int b = i * 16 + wid;
                __stcs(&out[(size_t)T_STEPS * BATCH +
                            ((size_t)s * BATCH + b0 + b) * HID + n0 + lane], tau_sv[i]);
            }
            if (s + 1 < T_STEPS) st_chunk(vx, zg, tid);   // slot 0: next x
        }
    }

    // ---- final: wait each group's last barrier, then reduce its y ----
#pragma unroll
    for (int gi = 0; gi < 2; gi++) {
        const int gb = g2 * 2 + gi;
        if (tid == 0) {
            unsigned v;
            do {
                asm volatile("ld.acquire.gpu.global.u32 %0, [%1];"
                             : "=r"(v) : "l"(&g_sense[gb]) : "memory");
            } while (v != lsense[gi]);
        }
        __syncthreads();
        if (tid < 32) {
            int r = tid >> 4, j = tid & 15;
            int b = gb * B_TILE + jn * 2 + r;
            float v = __ldcg(&g_ypart[1][b][j]);
#pragma unroll
            for (int o = 8; o; o >>= 1) v += __shfl_xor_sync(0xffffffffu, v, o);
            if (j == 0) out[(size_t)(T_STEPS - 1) * BATCH + b] = v + bo_v;
        }
    }
}

extern "C" void kernel_launch(void* const* d_in, const int* in_sizes, int n_in,
                              void* d_out, int out_size) {
    (void)in_sizes; (void)n_in; (void)out_size;
    const float* x_seq = (const float*)d_in[0];
    const float* Wc    = (const float*)d_in[1];
    const float* bc    = (const float*)d_in[2];
    const float* Wt    = (const float*)d_in[3];
    const float* bt    = (const float*)d_in[4];
    const float* Wo    = (const float*)d_in[5];
    const float* bo    = (const float*)d_in[6];
    float* out = (float*)d_out;

    cudaFuncSetAttribute(liquid_kernel, cudaFuncAttributeMaxDynamicSharedMemorySize, SMEM_BYTES);
    liquid_kernel<<<GRID, NTHREADS, SMEM_BYTES>>>(x_seq, Wc, bc, Wt, bt, Wo, bo, out);
}

// round 10
// speedup vs baseline: 2.0353x; 2.0353x over previous
#include <cuda_runtime.h>
#include <cuda_fp16.h>
#include <cstdint>

// Problem constants
#define T_STEPS 512
#define BATCH   256
#define DIN     128
#define HID     512
#define KTOT    640          // DIN + HID

// Tiling
#define P_B 8                // batch groups
#define P_N 16               // n-slices per group
#define B_TILE 32            // batch rows per CTA (M)
#define N_SLICE 32           // H columns per CTA
#define NCHUNK 5             // 640 / 128
#define NKG 8                // kg16 groups per chunk
#define KGG_TOT 40           // 640 / 16
#define NTHREADS 512
#define GRID (P_B * P_N)

// Shared memory layout (uint32 units)
// z slots: slot0/slot1 = x double buffer, slots 2..5 = h chunks 1..4
#define OFF_WF  0            // B frag staging: 40*4*32*4 = 20480 u32 (80KB)
#define OFF_Z   20480        // 6 slots * 2048 u32 = 12288 (48KB)
#define OFF_EPI 32768        // 4 wk-buffers * 32*66 = 8448
#define OFF_BC  41216        // 32
#define OFF_BT  41248        // 32
#define SMEM_U32 41280
#define SMEM_BYTES (SMEM_U32 * 4)   // 165120 B

#define ZBUF_BYTES 8192

// Persistent device state.
// g_hz: hidden state fp16, PRE-SWIZZLED smem fragment layout, [buf][group][chunk].
__device__ __align__(16) char g_hz[2][P_B][4][ZBUF_BYTES];
__device__ float    g_ypart[2][BATCH][P_N];
__device__ unsigned g_count[P_B];   // zero-init; returns to 0 each launch
__device__ unsigned g_sense[P_B];   // 512 toggles/launch -> back to 0 (replay-safe)

__device__ __forceinline__ void mma_f16(float* c, unsigned a0, unsigned a1,
                                        unsigned a2, unsigned a3,
                                        unsigned b0, unsigned b1) {
    asm("mma.sync.aligned.m16n8k16.row.col.f32.f16.f16.f32 "
        "{%0,%1,%2,%3},{%4,%5,%6,%7},{%8,%9},{%0,%1,%2,%3};"
        : "+f"(c[0]), "+f"(c[1]), "+f"(c[2]), "+f"(c[3])
        : "r"(a0), "r"(a1), "r"(a2), "r"(a3), "r"(b0), "r"(b1));
}

__device__ __forceinline__ void ldsm_x4(unsigned& a0, unsigned& a1,
                                        unsigned& a2, unsigned& a3, unsigned saddr) {
    asm volatile("ldmatrix.sync.aligned.m8n8.x4.shared.b16 {%0,%1,%2,%3}, [%4];"
                 : "=r"(a0), "=r"(a1), "=r"(a2), "=r"(a3) : "r"(saddr));
}

// Store one fp32 chunk into smem as fp16; XOR swizzle on the COMPLETE low-13-bit
// byte offset: (m*256 + k*2) ^ ((m&7)<<4). Used only for x chunks.
__device__ __forceinline__ void st_chunk(const float4* v, char* zbuf, int tid) {
#pragma unroll
    for (int i = 0; i < 2; i++) {
        int f  = i * NTHREADS + tid;
        int m  = f >> 5;
        int k4 = (f & 31) * 4;
        unsigned off = (unsigned)(m * 256 + k4 * 2) ^ (((unsigned)m & 7u) << 4);
        __half2 h01 = __float22half2_rn(make_float2(v[i].x, v[i].y));
        __half2 h23 = __float22half2_rn(make_float2(v[i].z, v[i].w));
        uint2 pk;
        pk.x = *(unsigned*)&h01;
        pk.y = *(unsigned*)&h23;
        *(uint2*)(zbuf + off) = pk;
    }
}

__global__ void __launch_bounds__(NTHREADS, 1)
liquid_kernel(const float* __restrict__ x_seq,
              const float* __restrict__ Wc, const float* __restrict__ bc,
              const float* __restrict__ Wt, const float* __restrict__ bt,
              const float* __restrict__ Wo, const float* __restrict__ bo,
              float* __restrict__ out) {
    extern __shared__ unsigned smem[];
    unsigned* sWf  = smem + OFF_WF;
    char*     sZ   = (char*)(smem + OFF_Z);
    float*    sEpi = (float*)(smem + OFF_EPI);
    float*    sBc  = (float*)(smem + OFF_BC);
    float*    sBt  = (float*)(smem + OFF_BT);

    const int tid  = threadIdx.x;
    const int gb   = blockIdx.x / P_N;
    const int jn   = blockIdx.x % P_N;
    const int b0   = gb * B_TILE;
    const int n0   = jn * N_SLICE;
    const int lane = tid & 31;
    const int wid  = tid >> 5;           // 0..15
    const int wm   = wid & 1;            // M half (16 rows)
    const int wn   = (wid >> 1) & 1;     // N half (32 combined cols)
    const int wk   = wid >> 2;           // K quarter (2 kg16 per chunk)

    // ---- init: weights into B-fragment layout (fp16) in smem staging ----
    for (int e = tid; e < KGG_TOT * 4 * 32 * 4; e += NTHREADS) {
        int q    = e & 3;
        int l    = (e >> 2) & 31;
        int ntp  = (e >> 7) & 3;
        int kgg  = e >> 9;
        int nt   = 2 * ntp + (q >> 1);
        int k0   = kgg * 16 + (l & 3) * 2 + (q & 1) * 8;
        int cc   = nt * 8 + (l >> 2);
        const float* W = (cc < N_SLICE) ? (Wc + n0 + cc) : (Wt + n0 + cc - N_SLICE);
        float w0 = W[(size_t)k0 * HID];
        float w1 = W[(size_t)(k0 + 1) * HID];
        __half2 h = __float22half2_rn(make_float2(w0, w1));
        sWf[e] = *(unsigned*)&h;
    }
    if (tid < N_SLICE) { sBc[tid] = bc[n0 + tid]; sBt[tid] = bt[n0 + tid]; }
    const float wo_v = Wo[n0 + lane];
    const float bo_v = bo[0];
    __syncthreads();

    // ---- this warp's B fragments -> REGISTERS (persistent) ----
    uint4 bf[10][2];
#pragma unroll
    for (int t = 0; t < 10; t++) {
        int kgg = (t >> 1) * NKG + wk * 2 + (t & 1);
#pragma unroll
        for (int tp = 0; tp < 2; tp++) {
            int ntp = wn * 2 + tp;
            bf[t][tp] = *(const uint4*)(sWf + ((kgg * 4 + ntp) * 32 + lane) * 4);
        }
    }

    // Per-thread staging coordinates for x chunks (step-invariant)
    const int sm0 = tid >> 5;
    const int sk0 = (tid & 31) * 4;
    const int sm1 = (NTHREADS + tid) >> 5;

    // ldmatrix base offsets; swizzle on complete low-13-bit offset; slot adds
    // bits 13+ (carry-free).
    const int arow = wm * 16 + ((lane >> 3) & 1) * 8 + (lane & 7);
    const int acol = ((lane >> 4) & 1) * 16;
    const unsigned zsh = (unsigned)__cvta_generic_to_shared(sZ);
    unsigned aoff[2];
#pragma unroll
    for (int i = 0; i < 2; i++) {
        int kg = wk * 2 + i;
        aoff[i] = zsh + (((unsigned)(arow * 256 + kg * 32 + acol)) ^
                         (((unsigned)arow & 7u) << 4));
    }

    // Epilogue h-store pointers
    const int hcol = n0 + lane;
    char* const hz_w0 = &g_hz[0][gb][hcol >> 7]
        [((unsigned)((wid) * 256 + (hcol & 127) * 2)) ^ (((unsigned)wid & 7u) << 4)];
    char* const hz_w1 = &g_hz[0][gb][hcol >> 7]
        [((unsigned)((16 + wid) * 256 + (hcol & 127) * 2)) ^ (((unsigned)(16 + wid) & 7u) << 4)];
    const size_t hz_buf_stride = (size_t)P_B * 4 * ZBUF_BYTES;

    float h_loc[2] = {0.f, 0.f};

    // Prologue: zero h slots (2..5) for step 0; stage x(0) into slot 0
    {
        uint4 z4 = make_uint4(0u, 0u, 0u, 0u);
#pragma unroll
        for (int c = 0; c < 4; c++)
            *((uint4*)(sZ + (2 + c) * ZBUF_BYTES) + tid) = z4;
        float4 vx0[2];
        const float* src = x_seq + (size_t)b0 * DIN;
        vx0[0] = *(const float4*)(src + (size_t)sm0 * DIN + sk0);
        vx0[1] = *(const float4*)(src + (size_t)sm1 * DIN + sk0);
        st_chunk(vx0, sZ, tid);
    }
    __syncthreads();

    unsigned lsense = 0;

    for (int s = 0; s < T_STEPS; s++) {
        const int p = s & 1;

        // ---- pre-wait: issue next x LDG (entire step to land) ----
        float4 vx[2];
        if (s + 1 < T_STEPS) {
            const float* src = x_seq + ((size_t)(s + 1) * BATCH + b0) * DIN;
            vx[0] = *(const float4*)(src + (size_t)sm0 * DIN + sk0);
            vx[1] = *(const float4*)(src + (size_t)sm1 * DIN + sk0);
        }

        // ---- WAIT for barrier(s-1): h(s) + y(s-1) become visible ----
        if (s > 0 && tid == 0) {
            unsigned v;
            do {
                asm volatile("ld.acquire.gpu.global.u32 %0, [%1];"
                             : "=r"(v) : "l"(&g_sense[gb]) : "memory");
            } while (v != lsense);
        }
        __syncthreads();

        // ---- issue h staging via cp.async (L2-direct, identity copy) ----
        if (s > 0) {
            const char* hb = &g_hz[p][gb][0][0] + (size_t)tid * 16;
            unsigned dst = zsh + 2u * ZBUF_BYTES + (unsigned)tid * 16u;
#pragma unroll
            for (int c = 0; c < 4; c++) {
                asm volatile("cp.async.cg.shared.global [%0], [%1], 16;"
                             :: "r"(dst + (unsigned)c * ZBUF_BYTES),
                                "l"(hb + (size_t)c * ZBUF_BYTES) : "memory");
            }
            asm volatile("cp.async.commit_group;" ::: "memory");
        }

        // ---- chunk-0 MMA (x slot p, staged last step) under the cp.async ----
        float acc[4][4] = {};
        const unsigned x0off = (unsigned)(p * ZBUF_BYTES);
#pragma unroll
        for (int t = 0; t < 2; t++) {
            unsigned a0, a1, a2, a3;
            ldsm_x4(a0, a1, a2, a3, aoff[t] + x0off);
#pragma unroll
            for (int tp = 0; tp < 2; tp++) {
                mma_f16(acc[tp * 2 + 0], a0, a1, a2, a3, bf[t][tp].x, bf[t][tp].y);
                mma_f16(acc[tp * 2 + 1], a0, a1, a2, a3, bf[t][tp].z, bf[t][tp].w);
            }
        }

        // ---- y reduce for previous step (warp 0, fills cp.async window) ----
        if (s > 0 && tid < 32) {
            int r = tid >> 4, j = tid & 15;
            int b = b0 + jn * 2 + r;
            float v = __ldcg(&g_ypart[p ^ 1][b][j]);
#pragma unroll
            for (int o = 8; o; o >>= 1) v += __shfl_xor_sync(0xffffffffu, v, o);
            if (j == 0) out[(size_t)(s - 1) * BATCH + b] = v + bo_v;
        }

        if (s > 0) asm volatile("cp.async.wait_group 0;" ::: "memory");
        __syncthreads();

        // ---- chunks 1..4 MMA (slots 2..5) ----
#pragma unroll
        for (int t = 2; t < 10; t++) {
            unsigned c = (unsigned)(t >> 1);           // 1..4
            unsigned a0, a1, a2, a3;
            ldsm_x4(a0, a1, a2, a3, aoff[t & 1] + (c + 1) * ZBUF_BYTES);
#pragma unroll
            for (int tp = 0; tp < 2; tp++) {
                mma_f16(acc[tp * 2 + 0], a0, a1, a2, a3, bf[t][tp].x, bf[t][tp].y);
                mma_f16(acc[tp * 2 + 1], a0, a1, a2, a3, bf[t][tp].z, bf[t][tp].w);
            }
        }

        // ---- scatter partial accumulators to per-wk epilogue buffers ----
        {
            float* eb = sEpi + wk * 2112;
            int row = wm * 16 + (lane >> 2);
#pragma unroll
            for (int t = 0; t < 4; t++) {
                int col = wn * 32 + t * 8 + (lane & 3) * 2;
                *(float2*)&eb[row * 66 + col]       = make_float2(acc[t][0], acc[t][1]);
                *(float2*)&eb[(row + 8) * 66 + col] = make_float2(acc[t][2], acc[t][3]);
            }
        }
        __syncthreads();

        // ---- epilogue: reduce wk partials, activations, h update ----
        float tau_sv[2];
        char* hz_base0 = hz_w0 + (size_t)(p ^ 1) * hz_buf_stride;
        char* hz_base1 = hz_w1 + (size_t)(p ^ 1) * hz_buf_stride;
#pragma unroll
        for (int i = 0; i < 2; i++) {
            int b  = i * 16 + wid;
            int nl = lane;
            float uc = sBc[nl], ut = sBt[nl];
#pragma unroll
            for (int q = 0; q < 4; q++) {
                uc += sEpi[q * 2112 + b * 66 + nl];
                ut += sEpi[q * 2112 + b * 66 + nl + 32];
            }
            float ea   = __expf(-2.f * fabsf(uc));
            float cand = copysignf(__fdividef(1.f - ea, 1.f + ea), uc);
            float sg   = __fdividef(1.f, 1.f + __expf(-ut));
            float tau  = 0.2f + 1.8f * sg;
            tau_sv[i]  = tau;
            float h    = h_loc[i];
            float hn   = h + 0.1f * __fdividef(cand - h, tau);
            h_loc[i]   = hn;
            *(__half*)(i == 0 ? hz_base0 : hz_base1) = __float2half_rn(hn);

            float pp = hn * wo_v;
#pragma unroll
            for (int o = 16; o; o >>= 1) pp += __shfl_xor_sync(0xffffffffu, pp, o);
            if (lane == 0) g_ypart[s & 1][b0 + b][jn] = pp;
        }

        // ---- ARRIVE (no wait); overlap tau stores + x staging ----
        __syncthreads();
        if (tid == 0) {
            lsense ^= 1u;
            unsigned old;
            asm volatile("atom.add.release.gpu.global.u32 %0, [%1], %2;"
                         : "=r"(old) : "l"(&g_count[gb]), "r"(1u) : "memory");
            if (old == P_N - 1u) {
                g_count[gb] = 0u;
                asm volatile("st.release.gpu.global.u32 [%0], %1;"
                             :: "l"(&g_sense[gb]), "r"(lsense) : "memory");
            }
        }
        // tau never read cross-CTA: store outside the ordered region.
#pragma unroll
        for (int i = 0; i < 2; i++) {
            int b = i * 16 + wid;
            __stcs(&out[(size_t)T_STEPS * BATCH +
                        ((size_t)s * BATCH + b0 + b) * HID + n0 + lane], tau_sv[i]);
        }
        if (s + 1 < T_STEPS) st_chunk(vx, sZ + (p ^ 1) * ZBUF_BYTES, tid);
        __syncthreads();
    }

    // ---- final: wait barrier(511), then reduce y(511) ----
    if (tid == 0) {
        unsigned v;
        do {
            asm volatile("ld.acquire.gpu.global.u32 %0, [%1];"
                         : "=r"(v) : "l"(&g_sense[gb]) : "memory");
        } while (v != lsense);
    }
    __syncthreads();
    if (tid < 32) {
        int r = tid >> 4, j = tid & 15;
        int b = b0 + jn * 2 + r;
        float v = __ldcg(&g_ypart[1][b][j]);
#pragma unroll
        for (int o = 8; o; o >>= 1) v += __shfl_xor_sync(0xffffffffu, v, o);
        if (j == 0) out[(size_t)(T_STEPS - 1) * BATCH + b] = v + bo_v;
    }
}

extern "C" void kernel_launch(void* const* d_in, const int* in_sizes, int n_in,
                              void* d_out, int out_size) {
    (void)in_sizes; (void)n_in; (void)out_size;
    const float* x_seq = (const float*)d_in[0];
    const float* Wc    = (const float*)d_in[1];
    const float* bc    = (const float*)d_in[2];
    const float* Wt    = (const float*)d_in[3];
    const float* bt    = (const float*)d_in[4];
    const float* Wo    = (const float*)d_in[5];
    const float* bo    = (const float*)d_in[6];
    float* out = (float*)d_out;

    cudaFuncSetAttribute(liquid_kernel, cudaFuncAttributeMaxDynamicSharedMemorySize, SMEM_BYTES);
    liquid_kernel<<<GRID, NTHREADS, SMEM_BYTES>>>(x_seq, Wc, bc, Wt, bt, Wo, bo, out);
}